// round 5
// baseline (speedup 1.0000x reference)
#include <cuda_runtime.h>
#include <cuda_bf16.h>
#include <cstdint>
#include <math.h>

// ---------------------------------------------------------------------------
// B=4, Q=K=4096, D=IN=256.
//   q=queries@Wq^T+bq ; k=keys@Wk^T+bk ; v=values@Wv^T+bv ; vT=v^T
//   S=q@k^T ; S=where(valid,S,-1e9)/16 ; P=softmax(S)
//   att=P@vT^T ; out=att@Wo^T+bo
// GEMMs: mma.sync m16n8k8 tf32 (fp32 accum).
// R5: CTA tile 256x128, warp tile 64x64 (4m x 2n warps) -> 0.125 smem-B/MAC,
// keeping total smem traffic (~88 B/cyc) under the 128 B/cyc crossbar at the
// 512 MAC/cyc/SM HMMA floor (R4's 64x32 warp tile needed ~160 B/cyc -> bound).
// ---------------------------------------------------------------------------

__device__ float g_q[4u * 4096u * 256u];
__device__ float g_k[4u * 4096u * 256u];
__device__ float g_v[4u * 4096u * 256u];
__device__ float g_vt[4u * 4096u * 256u];
__device__ float g_att[4u * 4096u * 256u];
__device__ float g_scores[67108864u];  // 4*4096*4096 fp32

// ======================= helpers =======================
__device__ __forceinline__ uint32_t smem_u32(const void* p) {
  uint32_t a;
  asm("{ .reg .u64 t; cvta.to.shared.u64 t, %1; cvt.u32.u64 %0, t; }"
      : "=r"(a) : "l"(p));
  return a;
}
__device__ __forceinline__ void cp16(uint32_t s, const void* g) {
  asm volatile("cp.async.cg.shared.global [%0], [%1], 16;\n" ::"r"(s), "l"(g));
}
__device__ __forceinline__ void cp_commit() {
  asm volatile("cp.async.commit_group;\n" ::: "memory");
}
template <int N>
__device__ __forceinline__ void cp_wait() {
  asm volatile("cp.async.wait_group %0;\n" ::"n"(N) : "memory");
}
__device__ __forceinline__ uint32_t f2tf32(float f) {
  uint32_t u;
  asm("cvt.rna.tf32.f32 %0, %1;" : "=r"(u) : "f"(f));
  return u;
}
__device__ __forceinline__ float roundtf32(float f) {
  return __uint_as_float(f2tf32(f));
}
__device__ __forceinline__ void mma8(float* d, const uint32_t* a, const uint32_t* b) {
  asm volatile(
      "mma.sync.aligned.m16n8k8.row.col.f32.tf32.tf32.f32 "
      "{%0,%1,%2,%3}, {%4,%5,%6,%7}, {%8,%9}, {%0,%1,%2,%3};"
      : "+f"(d[0]), "+f"(d[1]), "+f"(d[2]), "+f"(d[3])
      : "r"(a[0]), "r"(a[1]), "r"(a[2]), "r"(a[3]), "r"(b[0]), "r"(b[1]));
}

// ---------------------------------------------------------------------------
// tf32 tensor-core GEMM: C[M,N] = A[M,Kd] @ B[N,Kd]^T (+ bias)
// CTA tile 256x128, BK=32, 8 warps (4m x 2n), warp tile 64x64 (4x8 mma tiles).
// Smem per stage: A 256x36f (36864B) + B 128x36f (18432B) = 55296B; x2 stages.
// Stride 36 floats -> conflict-free fragment LDS.
// Requires M % 256 == 0, N % 128 == 0, Kd % 32 == 0.
// RIN:  round A/B to tf32 (rna) after LDS (raw-fp32 inputs).
// ROUT: round C to tf32 on store (downstream GEMMs skip RIN).
// ---------------------------------------------------------------------------
#define STAGE_BYTES 55296
#define B_OFF 36864

template <bool BIAS, bool RIN, bool ROUT>
__global__ void __launch_bounds__(256, 1) gemm_mma(
    const float* __restrict__ A, const float* __restrict__ B,
    const float* __restrict__ bias, float* __restrict__ C,
    int Kd, int ldA, int ldB, int ldC,
    long long sA, long long sB, long long sC) {
  extern __shared__ char dyn_smem[];
  const uint32_t smem_base = smem_u32(dyn_smem);
  const int tid = threadIdx.x;
  const int lane = tid & 31;
  const int wid = tid >> 5;
  const int wm = wid & 3;    // 0..3 -> 64-row quarter
  const int wn = wid >> 2;   // 0..1 -> 64-col half
  const long long z = blockIdx.z;
  const int bm = blockIdx.y * 256;
  const int bn = blockIdx.x * 128;

  const float* gA = A + z * sA + (size_t)bm * ldA;
  const float* gB = B + z * sB + (size_t)bn * ldB;

  float acc[4][8][4];
#pragma unroll
  for (int i = 0; i < 4; i++)
#pragma unroll
    for (int j = 0; j < 8; j++)
#pragma unroll
      for (int p = 0; p < 4; p++) acc[i][j][p] = 0.0f;

  const int ldRow = tid >> 3;  // 0..31
  const int ldCh = tid & 7;    // 16B chunk within 128B k-row

  auto load_tiles = [&](int stage, int k0) {
    uint32_t sa = smem_base + stage * STAGE_BYTES;
    uint32_t sb = smem_base + B_OFF + stage * STAGE_BYTES;
#pragma unroll
    for (int i = 0; i < 8; i++) {
      const int row = ldRow + i * 32;  // 0..255
      cp16(sa + row * 144 + ldCh * 16, gA + (size_t)row * ldA + k0 + ldCh * 4);
    }
#pragma unroll
    for (int i = 0; i < 4; i++) {
      const int row = ldRow + i * 32;  // 0..127
      cp16(sb + row * 144 + ldCh * 16, gB + (size_t)row * ldB + k0 + ldCh * 4);
    }
    cp_commit();
  };

  const int r = lane >> 2;  // groupID
  const int c = lane & 3;   // threadID_in_group

  const int KT = Kd >> 5;
  load_tiles(0, 0);
  for (int it = 0; it < KT; ++it) {
    const int buf = it & 1;
    if (it + 1 < KT) {
      load_tiles(buf ^ 1, (it + 1) << 5);
      cp_wait<1>();
    } else {
      cp_wait<0>();
    }
    __syncthreads();

    const float* As = (const float*)(dyn_smem + buf * STAGE_BYTES);
    const float* Bs = (const float*)(dyn_smem + B_OFF + buf * STAGE_BYTES);
    const float* aB = As + (wm * 64 + r) * 36 + c;
    const float* bB = Bs + (wn * 64 + r) * 36 + c;

#pragma unroll
    for (int ks = 0; ks < 4; ++ks) {
      uint32_t af[4][4], bf[8][2];
#pragma unroll
      for (int mt = 0; mt < 4; mt++) {
        const float* p = aB + mt * (16 * 36) + ks * 8;
        // a0:(r,c) a1:(r+8,c) a2:(r,c+4) a3:(r+8,c+4)
        float v0 = p[0], v1 = p[8 * 36], v2 = p[4], v3 = p[8 * 36 + 4];
        if (RIN) {
          af[mt][0] = f2tf32(v0); af[mt][1] = f2tf32(v1);
          af[mt][2] = f2tf32(v2); af[mt][3] = f2tf32(v3);
        } else {
          af[mt][0] = __float_as_uint(v0); af[mt][1] = __float_as_uint(v1);
          af[mt][2] = __float_as_uint(v2); af[mt][3] = __float_as_uint(v3);
        }
      }
#pragma unroll
      for (int nt = 0; nt < 8; nt++) {
        const float* p = bB + nt * (8 * 36) + ks * 8;
        // b0:(k=c, n=r)  b1:(k=c+4, n=r)
        float v0 = p[0], v1 = p[4];
        if (RIN) {
          bf[nt][0] = f2tf32(v0); bf[nt][1] = f2tf32(v1);
        } else {
          bf[nt][0] = __float_as_uint(v0); bf[nt][1] = __float_as_uint(v1);
        }
      }
#pragma unroll
      for (int mt = 0; mt < 4; mt++)
#pragma unroll
        for (int nt = 0; nt < 8; nt++) mma8(acc[mt][nt], af[mt], bf[nt]);
    }
    __syncthreads();
  }

  // Epilogue
  float* Cz = C + z * sC;
  const int c2 = (lane & 3) * 2;
#pragma unroll
  for (int mt = 0; mt < 4; mt++) {
    const int row0 = bm + wm * 64 + mt * 16 + r;
#pragma unroll
    for (int nt = 0; nt < 8; nt++) {
      const int col = bn + wn * 64 + nt * 8 + c2;
      float d0 = acc[mt][nt][0], d1 = acc[mt][nt][1];
      float d2 = acc[mt][nt][2], d3 = acc[mt][nt][3];
      if (BIAS) {
        const float b0 = bias[col], b1 = bias[col + 1];
        d0 += b0; d1 += b1; d2 += b0; d3 += b1;
      }
      if (ROUT) {
        d0 = roundtf32(d0); d1 = roundtf32(d1);
        d2 = roundtf32(d2); d3 = roundtf32(d3);
      }
      float2 v0; v0.x = d0; v0.y = d1;
      float2 v1; v1.x = d2; v1.y = d3;
      *(float2*)(Cz + (size_t)row0 * ldC + col) = v0;
      *(float2*)(Cz + (size_t)(row0 + 8) * ldC + col) = v1;
    }
  }
}

// ---------------------------------------------------------------------------
// Batched transpose: vt[b][n][k] = v[b][k][n]   (k=4096, n=256)
// ---------------------------------------------------------------------------
__global__ __launch_bounds__(256) void transpose_kernel(
    const float* __restrict__ v, float* __restrict__ vt) {
  __shared__ float t[32][33];
  const int b = blockIdx.z;
  const int k0 = blockIdx.x * 32;
  const int n0 = blockIdx.y * 32;
  const int tx = threadIdx.x & 31;
  const int ty = threadIdx.x >> 5;  // 0..7
  const float* src = v + (size_t)b * 4096 * 256;
  float* dst = vt + (size_t)b * 256 * 4096;
#pragma unroll
  for (int i = 0; i < 32; i += 8)
    t[ty + i][tx] = src[(size_t)(k0 + ty + i) * 256 + n0 + tx];
  __syncthreads();
#pragma unroll
  for (int i = 0; i < 32; i += 8)
    dst[(size_t)(n0 + ty + i) * 4096 + k0 + tx] = t[tx][ty + i];
}

// ---------------------------------------------------------------------------
// Fused length-mask + scale(1/16) + softmax, in place. Writes tf32-rounded
// probs so the PV GEMM consumes them without per-fragment cvt.
// ---------------------------------------------------------------------------
__global__ __launch_bounds__(256) void softmax_mask_kernel(
    float* __restrict__ scores, const int* __restrict__ mask) {
  const size_t row = blockIdx.x;
  const int len = mask[row];
  float* r = scores + row * 4096u;
  const int t = threadIdx.x;
  const int lane = t & 31;
  const int wid = t >> 5;

  __shared__ float sred[8];

  const float scale = 0.0625f;
  float v[16];
  float mx = -1e30f;
#pragma unroll
  for (int i = 0; i < 16; i++) {
    const int kk = t + i * 256;
    float s = (kk < len) ? r[kk] * scale : -1e30f;
    v[i] = s;
    mx = fmaxf(mx, s);
  }
#pragma unroll
  for (int o = 16; o; o >>= 1) mx = fmaxf(mx, __shfl_xor_sync(0xffffffffu, mx, o));
  if (lane == 0) sred[wid] = mx;
  __syncthreads();
  float bm = sred[0];
#pragma unroll
  for (int w = 1; w < 8; w++) bm = fmaxf(bm, sred[w]);
  __syncthreads();

  float e[16];
  float sum = 0.0f;
#pragma unroll
  for (int i = 0; i < 16; i++) {
    e[i] = __expf(v[i] - bm);
    sum += e[i];
  }
#pragma unroll
  for (int o = 16; o; o >>= 1) sum += __shfl_xor_sync(0xffffffffu, sum, o);
  if (lane == 0) sred[wid] = sum;
  __syncthreads();
  float bs = 0.0f;
#pragma unroll
  for (int w = 0; w < 8; w++) bs += sred[w];
  const float inv = 1.0f / bs;

#pragma unroll
  for (int i = 0; i < 16; i++) {
    const int kk = t + i * 256;
    r[kk] = roundtf32(e[i] * inv);
  }
}

// ---------------------------------------------------------------------------
// Launch
// ---------------------------------------------------------------------------
extern "C" void kernel_launch(void* const* d_in, const int* in_sizes, int n_in,
                              void* d_out, int out_size) {
  const float* queries = (const float*)d_in[0];
  const float* keys    = (const float*)d_in[1];
  const float* values  = (const float*)d_in[2];
  const int*   mask    = (const int*)d_in[3];
  const float* Wq = (const float*)d_in[4];
  const float* bq = (const float*)d_in[5];
  const float* Wk = (const float*)d_in[6];
  const float* bk = (const float*)d_in[7];
  const float* Wv = (const float*)d_in[8];
  const float* bv = (const float*)d_in[9];
  const float* Wo = (const float*)d_in[10];
  const float* bo = (const float*)d_in[11];
  float* out = (float*)d_out;

  float *q, *k, *v, *vt, *att, *sc;
  cudaGetSymbolAddress((void**)&q, g_q);
  cudaGetSymbolAddress((void**)&k, g_k);
  cudaGetSymbolAddress((void**)&v, g_v);
  cudaGetSymbolAddress((void**)&vt, g_vt);
  cudaGetSymbolAddress((void**)&att, g_att);
  cudaGetSymbolAddress((void**)&sc, g_scores);

  const int SMEM = 2 * STAGE_BYTES;  // 110592
  cudaFuncSetAttribute(gemm_mma<true, true, true>,
                       cudaFuncAttributeMaxDynamicSharedMemorySize, SMEM);
  cudaFuncSetAttribute(gemm_mma<false, false, false>,
                       cudaFuncAttributeMaxDynamicSharedMemorySize, SMEM);
  cudaFuncSetAttribute(gemm_mma<true, true, false>,
                       cudaFuncAttributeMaxDynamicSharedMemorySize, SMEM);

  dim3 blk(256);
  const long long QD = 4096LL * 256;
  const long long QK = 4096LL * 4096;

  // Projections: X[16384,256] @ W[256,256]^T + b ; round in (raw fp32) and out
  dim3 gProj(2, 64, 1);  // N/128, M/256
  gemm_mma<true, true, true><<<gProj, blk, SMEM>>>(
      queries, Wq, bq, q, 256, 256, 256, 256, 0, 0, 0);
  gemm_mma<true, true, true><<<gProj, blk, SMEM>>>(
      keys, Wk, bk, k, 256, 256, 256, 256, 0, 0, 0);
  gemm_mma<true, true, true><<<gProj, blk, SMEM>>>(
      values, Wv, bv, v, 256, 256, 256, 256, 0, 0, 0);

  // vT for PV GEMM (K-major B operand)
  transpose_kernel<<<dim3(128, 8, 4), blk>>>(v, vt);

  // Scores: per batch, S[4096,4096] = q @ k^T  (inputs pre-rounded, no cvt)
  gemm_mma<false, false, false><<<dim3(32, 16, 4), blk, SMEM>>>(
      q, k, nullptr, sc, 256, 256, 256, 4096, QD, QD, QK);

  // Mask + scale + softmax (in place, writes tf32-rounded probs)
  softmax_mask_kernel<<<16384, 256>>>(sc, mask);

  // att: per batch, att[4096,256] = P[4096,4096] @ vT[256,4096]^T
  gemm_mma<false, false, false><<<dim3(2, 16, 4), blk, SMEM>>>(
      sc, vt, nullptr, att, 4096, 4096, 4096, 256, QK, QD, QD);

  // Output projection: out = att @ Wo^T + bo  (Wo raw -> round inputs)
  gemm_mma<true, true, false><<<gProj, blk, SMEM>>>(
      att, Wo, bo, out, 256, 256, 256, 256, 0, 0, 0);
}

// round 6
// speedup vs baseline: 1.0102x; 1.0102x over previous
#include <cuda_runtime.h>
#include <cuda_bf16.h>
#include <cstdint>
#include <math.h>

// ---------------------------------------------------------------------------
// B=4, Q=K=4096, D=IN=256.
//   q=queries@Wq^T+bq ; k=keys@Wk^T+bk ; v=values@Wv^T+bv ; vT=v^T
//   S=q@k^T ; S=where(valid,S,-1e9)/16 ; P=softmax(S)
//   att=P@vT^T ; out=att@Wo^T+bo
// GEMMs: mma.sync m16n8k8 tf32 (fp32 accum).
// R6: CTA 128x128x32 (2 CTAs/SM for latency hiding, like R4) but 4 warps of
// 64x64 (0.125 smem-B/MAC, like R5) -> smem traffic ~1536 cyc/iter vs MMA
// 2048 cyc/iter per SM: MMA-bound instead of crossbar-co-bound.
// ---------------------------------------------------------------------------

__device__ float g_q[4u * 4096u * 256u];
__device__ float g_k[4u * 4096u * 256u];
__device__ float g_v[4u * 4096u * 256u];
__device__ float g_vt[4u * 4096u * 256u];
__device__ float g_att[4u * 4096u * 256u];
__device__ float g_scores[67108864u];  // 4*4096*4096 fp32

// ======================= helpers =======================
__device__ __forceinline__ uint32_t smem_u32(const void* p) {
  uint32_t a;
  asm("{ .reg .u64 t; cvta.to.shared.u64 t, %1; cvt.u32.u64 %0, t; }"
      : "=r"(a) : "l"(p));
  return a;
}
__device__ __forceinline__ void cp16(uint32_t s, const void* g) {
  asm volatile("cp.async.cg.shared.global [%0], [%1], 16;\n" ::"r"(s), "l"(g));
}
__device__ __forceinline__ void cp_commit() {
  asm volatile("cp.async.commit_group;\n" ::: "memory");
}
template <int N>
__device__ __forceinline__ void cp_wait() {
  asm volatile("cp.async.wait_group %0;\n" ::"n"(N) : "memory");
}
__device__ __forceinline__ uint32_t f2tf32(float f) {
  uint32_t u;
  asm("cvt.rna.tf32.f32 %0, %1;" : "=r"(u) : "f"(f));
  return u;
}
__device__ __forceinline__ float roundtf32(float f) {
  return __uint_as_float(f2tf32(f));
}
__device__ __forceinline__ void mma8(float* d, const uint32_t* a, const uint32_t* b) {
  asm volatile(
      "mma.sync.aligned.m16n8k8.row.col.f32.tf32.tf32.f32 "
      "{%0,%1,%2,%3}, {%4,%5,%6,%7}, {%8,%9}, {%0,%1,%2,%3};"
      : "+f"(d[0]), "+f"(d[1]), "+f"(d[2]), "+f"(d[3])
      : "r"(a[0]), "r"(a[1]), "r"(a[2]), "r"(a[3]), "r"(b[0]), "r"(b[1]));
}

// ---------------------------------------------------------------------------
// tf32 tensor-core GEMM: C[M,N] = A[M,Kd] @ B[N,Kd]^T (+ bias)
// CTA tile 128x128, BK=32, 4 warps (2m x 2n), warp tile 64x64 (4x8 mma tiles).
// Smem per stage: A 128x36f + B 128x36f = 36864B; x2 stages = 73728B.
// Stride 36 floats -> conflict-free fragment LDS.
// Requires M,N % 128 == 0, Kd % 32 == 0.
// RIN:  round A/B to tf32 (rna) after LDS (raw-fp32 inputs).
// ROUT: round C to tf32 on store (downstream GEMMs skip RIN).
// ---------------------------------------------------------------------------
#define STAGE_BYTES 36864
#define B_OFF 18432

template <bool BIAS, bool RIN, bool ROUT>
__global__ void __launch_bounds__(128, 2) gemm_mma(
    const float* __restrict__ A, const float* __restrict__ B,
    const float* __restrict__ bias, float* __restrict__ C,
    int Kd, int ldA, int ldB, int ldC,
    long long sA, long long sB, long long sC) {
  extern __shared__ char dyn_smem[];
  const uint32_t smem_base = smem_u32(dyn_smem);
  const int tid = threadIdx.x;
  const int lane = tid & 31;
  const int wid = tid >> 5;  // 0..3
  const int wm = wid & 1;    // 0..1 -> 64-row half
  const int wn = wid >> 1;   // 0..1 -> 64-col half
  const long long z = blockIdx.z;
  const int bm = blockIdx.y * 128;
  const int bn = blockIdx.x * 128;

  const float* gA = A + z * sA + (size_t)bm * ldA;
  const float* gB = B + z * sB + (size_t)bn * ldB;

  float acc[4][8][4];
#pragma unroll
  for (int i = 0; i < 4; i++)
#pragma unroll
    for (int j = 0; j < 8; j++)
#pragma unroll
      for (int p = 0; p < 4; p++) acc[i][j][p] = 0.0f;

  const int ldRow = tid >> 3;  // 0..15
  const int ldCh = tid & 7;    // 16B chunk within 128B k-row

  auto load_tiles = [&](int stage, int k0) {
    uint32_t sa = smem_base + stage * STAGE_BYTES;
    uint32_t sb = sa + B_OFF;
#pragma unroll
    for (int i = 0; i < 8; i++) {
      const int row = ldRow + i * 16;  // 0..127
      cp16(sa + row * 144 + ldCh * 16, gA + (size_t)row * ldA + k0 + ldCh * 4);
      cp16(sb + row * 144 + ldCh * 16, gB + (size_t)row * ldB + k0 + ldCh * 4);
    }
    cp_commit();
  };

  const int r = lane >> 2;  // groupID
  const int c = lane & 3;   // threadID_in_group

  const int KT = Kd >> 5;
  load_tiles(0, 0);
  for (int it = 0; it < KT; ++it) {
    const int buf = it & 1;
    if (it + 1 < KT) {
      load_tiles(buf ^ 1, (it + 1) << 5);
      cp_wait<1>();
    } else {
      cp_wait<0>();
    }
    __syncthreads();

    const float* As = (const float*)(dyn_smem + buf * STAGE_BYTES);
    const float* Bs = (const float*)(dyn_smem + buf * STAGE_BYTES + B_OFF);
    const float* aB = As + (wm * 64 + r) * 36 + c;
    const float* bB = Bs + (wn * 64 + r) * 36 + c;

#pragma unroll
    for (int ks = 0; ks < 4; ++ks) {
      uint32_t af[4][4], bf[8][2];
#pragma unroll
      for (int mt = 0; mt < 4; mt++) {
        const float* p = aB + mt * (16 * 36) + ks * 8;
        // a0:(r,c) a1:(r+8,c) a2:(r,c+4) a3:(r+8,c+4)
        float v0 = p[0], v1 = p[8 * 36], v2 = p[4], v3 = p[8 * 36 + 4];
        if (RIN) {
          af[mt][0] = f2tf32(v0); af[mt][1] = f2tf32(v1);
          af[mt][2] = f2tf32(v2); af[mt][3] = f2tf32(v3);
        } else {
          af[mt][0] = __float_as_uint(v0); af[mt][1] = __float_as_uint(v1);
          af[mt][2] = __float_as_uint(v2); af[mt][3] = __float_as_uint(v3);
        }
      }
#pragma unroll
      for (int nt = 0; nt < 8; nt++) {
        const float* p = bB + nt * (8 * 36) + ks * 8;
        // b0:(k=c, n=r)  b1:(k=c+4, n=r)
        float v0 = p[0], v1 = p[4];
        if (RIN) {
          bf[nt][0] = f2tf32(v0); bf[nt][1] = f2tf32(v1);
        } else {
          bf[nt][0] = __float_as_uint(v0); bf[nt][1] = __float_as_uint(v1);
        }
      }
#pragma unroll
      for (int mt = 0; mt < 4; mt++)
#pragma unroll
        for (int nt = 0; nt < 8; nt++) mma8(acc[mt][nt], af[mt], bf[nt]);
    }
    __syncthreads();
  }

  // Epilogue
  float* Cz = C + z * sC;
  const int c2 = (lane & 3) * 2;
#pragma unroll
  for (int mt = 0; mt < 4; mt++) {
    const int row0 = bm + wm * 64 + mt * 16 + r;
#pragma unroll
    for (int nt = 0; nt < 8; nt++) {
      const int col = bn + wn * 64 + nt * 8 + c2;
      float d0 = acc[mt][nt][0], d1 = acc[mt][nt][1];
      float d2 = acc[mt][nt][2], d3 = acc[mt][nt][3];
      if (BIAS) {
        const float b0 = bias[col], b1 = bias[col + 1];
        d0 += b0; d1 += b1; d2 += b0; d3 += b1;
      }
      if (ROUT) {
        d0 = roundtf32(d0); d1 = roundtf32(d1);
        d2 = roundtf32(d2); d3 = roundtf32(d3);
      }
      float2 v0; v0.x = d0; v0.y = d1;
      float2 v1; v1.x = d2; v1.y = d3;
      *(float2*)(Cz + (size_t)row0 * ldC + col) = v0;
      *(float2*)(Cz + (size_t)(row0 + 8) * ldC + col) = v1;
    }
  }
}

// ---------------------------------------------------------------------------
// Batched transpose: vt[b][n][k] = v[b][k][n]   (k=4096, n=256)
// ---------------------------------------------------------------------------
__global__ __launch_bounds__(256) void transpose_kernel(
    const float* __restrict__ v, float* __restrict__ vt) {
  __shared__ float t[32][33];
  const int b = blockIdx.z;
  const int k0 = blockIdx.x * 32;
  const int n0 = blockIdx.y * 32;
  const int tx = threadIdx.x & 31;
  const int ty = threadIdx.x >> 5;  // 0..7
  const float* src = v + (size_t)b * 4096 * 256;
  float* dst = vt + (size_t)b * 256 * 4096;
#pragma unroll
  for (int i = 0; i < 32; i += 8)
    t[ty + i][tx] = src[(size_t)(k0 + ty + i) * 256 + n0 + tx];
  __syncthreads();
#pragma unroll
  for (int i = 0; i < 32; i += 8)
    dst[(size_t)(n0 + ty + i) * 4096 + k0 + tx] = t[tx][ty + i];
}

// ---------------------------------------------------------------------------
// Fused length-mask + scale(1/16) + softmax, in place. Writes tf32-rounded
// probs so the PV GEMM consumes them without per-fragment cvt.
// ---------------------------------------------------------------------------
__global__ __launch_bounds__(256) void softmax_mask_kernel(
    float* __restrict__ scores, const int* __restrict__ mask) {
  const size_t row = blockIdx.x;
  const int len = mask[row];
  float* r = scores + row * 4096u;
  const int t = threadIdx.x;
  const int lane = t & 31;
  const int wid = t >> 5;

  __shared__ float sred[8];

  const float scale = 0.0625f;
  float v[16];
  float mx = -1e30f;
#pragma unroll
  for (int i = 0; i < 16; i++) {
    const int kk = t + i * 256;
    float s = (kk < len) ? r[kk] * scale : -1e30f;
    v[i] = s;
    mx = fmaxf(mx, s);
  }
#pragma unroll
  for (int o = 16; o; o >>= 1) mx = fmaxf(mx, __shfl_xor_sync(0xffffffffu, mx, o));
  if (lane == 0) sred[wid] = mx;
  __syncthreads();
  float bm = sred[0];
#pragma unroll
  for (int w = 1; w < 8; w++) bm = fmaxf(bm, sred[w]);
  __syncthreads();

  float e[16];
  float sum = 0.0f;
#pragma unroll
  for (int i = 0; i < 16; i++) {
    e[i] = __expf(v[i] - bm);
    sum += e[i];
  }
#pragma unroll
  for (int o = 16; o; o >>= 1) sum += __shfl_xor_sync(0xffffffffu, sum, o);
  if (lane == 0) sred[wid] = sum;
  __syncthreads();
  float bs = 0.0f;
#pragma unroll
  for (int w = 0; w < 8; w++) bs += sred[w];
  const float inv = 1.0f / bs;

#pragma unroll
  for (int i = 0; i < 16; i++) {
    const int kk = t + i * 256;
    r[kk] = roundtf32(e[i] * inv);
  }
}

// ---------------------------------------------------------------------------
// Launch
// ---------------------------------------------------------------------------
extern "C" void kernel_launch(void* const* d_in, const int* in_sizes, int n_in,
                              void* d_out, int out_size) {
  const float* queries = (const float*)d_in[0];
  const float* keys    = (const float*)d_in[1];
  const float* values  = (const float*)d_in[2];
  const int*   mask    = (const int*)d_in[3];
  const float* Wq = (const float*)d_in[4];
  const float* bq = (const float*)d_in[5];
  const float* Wk = (const float*)d_in[6];
  const float* bk = (const float*)d_in[7];
  const float* Wv = (const float*)d_in[8];
  const float* bv = (const float*)d_in[9];
  const float* Wo = (const float*)d_in[10];
  const float* bo = (const float*)d_in[11];
  float* out = (float*)d_out;

  float *q, *k, *v, *vt, *att, *sc;
  cudaGetSymbolAddress((void**)&q, g_q);
  cudaGetSymbolAddress((void**)&k, g_k);
  cudaGetSymbolAddress((void**)&v, g_v);
  cudaGetSymbolAddress((void**)&vt, g_vt);
  cudaGetSymbolAddress((void**)&att, g_att);
  cudaGetSymbolAddress((void**)&sc, g_scores);

  const int SMEM = 2 * STAGE_BYTES;  // 73728
  cudaFuncSetAttribute(gemm_mma<true, true, true>,
                       cudaFuncAttributeMaxDynamicSharedMemorySize, SMEM);
  cudaFuncSetAttribute(gemm_mma<false, false, false>,
                       cudaFuncAttributeMaxDynamicSharedMemorySize, SMEM);
  cudaFuncSetAttribute(gemm_mma<true, true, false>,
                       cudaFuncAttributeMaxDynamicSharedMemorySize, SMEM);

  dim3 blk(128);
  const long long QD = 4096LL * 256;
  const long long QK = 4096LL * 4096;

  // Projections: X[16384,256] @ W[256,256]^T + b ; round in (raw fp32) and out
  dim3 gProj(2, 128, 1);  // N/128, M/128
  gemm_mma<true, true, true><<<gProj, blk, SMEM>>>(
      queries, Wq, bq, q, 256, 256, 256, 256, 0, 0, 0);
  gemm_mma<true, true, true><<<gProj, blk, SMEM>>>(
      keys, Wk, bk, k, 256, 256, 256, 256, 0, 0, 0);
  gemm_mma<true, true, true><<<gProj, blk, SMEM>>>(
      values, Wv, bv, v, 256, 256, 256, 256, 0, 0, 0);

  // vT for PV GEMM (K-major B operand)
  transpose_kernel<<<dim3(128, 8, 4), dim3(256)>>>(v, vt);

  // Scores: per batch, S[4096,4096] = q @ k^T  (inputs pre-rounded, no cvt)
  gemm_mma<false, false, false><<<dim3(32, 32, 4), blk, SMEM>>>(
      q, k, nullptr, sc, 256, 256, 256, 4096, QD, QD, QK);

  // Mask + scale + softmax (in place, writes tf32-rounded probs)
  softmax_mask_kernel<<<16384, 256>>>(sc, mask);

  // att: per batch, att[4096,256] = P[4096,4096] @ vT[256,4096]^T
  gemm_mma<false, false, false><<<dim3(2, 32, 4), blk, SMEM>>>(
      sc, vt, nullptr, att, 4096, 4096, 4096, 256, QK, QD, QD);

  // Output projection: out = att @ Wo^T + bo  (Wo raw -> round inputs)
  gemm_mma<true, true, false><<<gProj, blk, SMEM>>>(
      att, Wo, bo, out, 256, 256, 256, 256, 0, 0, 0);
}

// round 7
// speedup vs baseline: 1.0666x; 1.0559x over previous
#include <cuda_runtime.h>
#include <cuda_fp16.h>
#include <cstdint>
#include <math.h>

// ---------------------------------------------------------------------------
// B=4, Q=K=4096, D=IN=256.
//   q=queries@Wq^T+bq ; k=keys@Wk^T+bk ; v=values@Wv^T+bv ; vT=v^T
//   S=q@k^T (fp32) ; S=where(valid,S,-1e9)/16 ; P=softmax(S) -> half
//   att=P@vT^T ; out=att@Wo^T+bo
// R7: all GEMMs via mma.sync.m16n8k16 f16 (fp32 accum). tf32 legacy HMMA
// measured at ~256 MAC/cyc/SM (GEMMs ~450us for 34.4G MAC); fp16 legacy path
// is expected 2x that. fp16 mantissa == tf32 mantissa (11 bits) so accuracy
// stays ~1e-4 territory. Scores kept fp32 through softmax.
// ---------------------------------------------------------------------------

// scratch (static __device__: allocation-guard safe)
__device__ __half g_xq[4u * 4096u * 256u];
__device__ __half g_xk[4u * 4096u * 256u];
__device__ __half g_xv[4u * 4096u * 256u];
__device__ __half g_wq[65536], g_wk[65536], g_wv[65536], g_wo[65536];
__device__ __half g_qh[4u * 4096u * 256u];
__device__ __half g_kh[4u * 4096u * 256u];
__device__ __half g_vh[4u * 4096u * 256u];
__device__ __half g_vth[4u * 4096u * 256u];
__device__ __half g_atth[4u * 4096u * 256u];
__device__ __half g_ph[67108864u];   // probs, half, 128MB
__device__ float g_scores[67108864u];  // scores, fp32, 256MB

// ======================= helpers =======================
__device__ __forceinline__ uint32_t smem_u32(const void* p) {
  uint32_t a;
  asm("{ .reg .u64 t; cvta.to.shared.u64 t, %1; cvt.u32.u64 %0, t; }"
      : "=r"(a) : "l"(p));
  return a;
}
__device__ __forceinline__ void cp16(uint32_t s, const void* g) {
  asm volatile("cp.async.cg.shared.global [%0], [%1], 16;\n" ::"r"(s), "l"(g));
}
__device__ __forceinline__ void cp_commit() {
  asm volatile("cp.async.commit_group;\n" ::: "memory");
}
template <int N>
__device__ __forceinline__ void cp_wait() {
  asm volatile("cp.async.wait_group %0;\n" ::"n"(N) : "memory");
}
__device__ __forceinline__ void mma16(float* d, const uint32_t* a, const uint32_t* b) {
  asm volatile(
      "mma.sync.aligned.m16n8k16.row.col.f32.f16.f16.f32 "
      "{%0,%1,%2,%3}, {%4,%5,%6,%7}, {%8,%9}, {%0,%1,%2,%3};"
      : "+f"(d[0]), "+f"(d[1]), "+f"(d[2]), "+f"(d[3])
      : "r"(a[0]), "r"(a[1]), "r"(a[2]), "r"(a[3]), "r"(b[0]), "r"(b[1]));
}
// epilogue store pair (col, col+1)
__device__ __forceinline__ void store2(float* p, float d0, float d1) {
  float2 v; v.x = d0; v.y = d1;
  *(float2*)p = v;
}
__device__ __forceinline__ void store2(__half* p, float d0, float d1) {
  *(__half2*)p = __floats2half2_rn(d0, d1);
}

// ---------------------------------------------------------------------------
// fp16 tensor-core GEMM: C[M,N] = A[M,Kd] @ B[N,Kd]^T (+ bias, fp32)
// A,B half; C float or half. CTA tile 128x128, BK=32 halves, 8 warps (2m x 4n),
// warp tile 64x32 (4x4 mma tiles), 2 k-steps of 16 per iter, double buffer.
// Smem rows padded: stride 20 words (32 halves data + 8 pad):
//   - fragment LDS.32 banks (g*20+c) mod 32 -> all 32 distinct, conflict-free
//   - cp.async stores row=lane: banks lane*20 mod 32 distinct per quarter-warp
// Requires M,N % 128 == 0, Kd % 32 == 0.
// ---------------------------------------------------------------------------
#define S32 20                       // words per smem row
#define TILE_WORDS (128 * S32)       // 2560 words = 10240 B
#define STAGE_BYTES (2 * TILE_WORDS * 4)  // A+B = 20480 B
#define SMEM_TOTAL (2 * STAGE_BYTES)      // 40960 B

template <bool BIAS, typename OutT>
__global__ void __launch_bounds__(256, 2) hgemm(
    const __half* __restrict__ A, const __half* __restrict__ B,
    const float* __restrict__ bias, OutT* __restrict__ C,
    int Kd, int ldA, int ldB, int ldC,
    long long sA, long long sB, long long sC) {
  extern __shared__ char dyn_smem[];
  const uint32_t smem_base = smem_u32(dyn_smem);
  const int tid = threadIdx.x;
  const int lane = tid & 31;
  const int wid = tid >> 5;
  const int wm = wid & 1;   // 0..1 -> 64-row half
  const int wn = wid >> 1;  // 0..3 -> 32-col quarter
  const long long z = blockIdx.z;
  const int bm = blockIdx.y * 128;
  const int bn = blockIdx.x * 128;

  const __half* gA = A + z * sA + (size_t)bm * ldA;
  const __half* gB = B + z * sB + (size_t)bn * ldB;

  float acc[4][4][4];
#pragma unroll
  for (int i = 0; i < 4; i++)
#pragma unroll
    for (int j = 0; j < 4; j++)
#pragma unroll
      for (int p = 0; p < 4; p++) acc[i][j][p] = 0.0f;

  // loader: threads 0-127 -> A rows, 128-255 -> B rows; 4 x cp16 per thread
  const int ldRow = tid & 127;
  const bool isB = tid >= 128;
  const __half* gRowBase = (isB ? gB : gA);
  const int ldLd = isB ? ldB : ldA;
  const uint32_t sRowOff = (isB ? STAGE_BYTES / 2 : 0) + ldRow * (S32 * 4);

  auto load_tiles = [&](int stage, int k0) {
    const uint32_t s0 = smem_base + stage * STAGE_BYTES + sRowOff;
    const __half* g0 = gRowBase + (size_t)ldRow * ldLd + k0;
#pragma unroll
    for (int ch = 0; ch < 4; ch++) cp16(s0 + ch * 16, g0 + ch * 8);
    cp_commit();
  };

  const int g = lane >> 2;  // groupID
  const int c = lane & 3;   // threadID_in_group

  const int KT = Kd >> 5;
  load_tiles(0, 0);
  for (int it = 0; it < KT; ++it) {
    const int buf = it & 1;
    if (it + 1 < KT) {
      load_tiles(buf ^ 1, (it + 1) << 5);
      cp_wait<1>();
    } else {
      cp_wait<0>();
    }
    __syncthreads();

    const uint32_t* As32 = (const uint32_t*)(dyn_smem + buf * STAGE_BYTES);
    const uint32_t* Bs32 = As32 + TILE_WORDS;

#pragma unroll
    for (int kk = 0; kk < 2; ++kk) {
      const int ko = kk * 8;
      uint32_t af[4][4], bf[4][2];
#pragma unroll
      for (int mt = 0; mt < 4; mt++) {
        const int base = (wm * 64 + mt * 16 + g) * S32 + c + ko;
        af[mt][0] = As32[base];
        af[mt][1] = As32[base + 8 * S32];
        af[mt][2] = As32[base + 4];
        af[mt][3] = As32[base + 8 * S32 + 4];
      }
#pragma unroll
      for (int nt = 0; nt < 4; nt++) {
        const int base = (wn * 32 + nt * 8 + g) * S32 + c + ko;
        bf[nt][0] = Bs32[base];
        bf[nt][1] = Bs32[base + 4];
      }
#pragma unroll
      for (int mt = 0; mt < 4; mt++)
#pragma unroll
        for (int nt = 0; nt < 4; nt++) mma16(acc[mt][nt], af[mt], bf[nt]);
    }
    __syncthreads();
  }

  // Epilogue
  OutT* Cz = C + z * sC;
  const int c2 = c * 2;
#pragma unroll
  for (int mt = 0; mt < 4; mt++) {
    const int row0 = bm + wm * 64 + mt * 16 + g;
#pragma unroll
    for (int nt = 0; nt < 4; nt++) {
      const int col = bn + wn * 32 + nt * 8 + c2;
      float d0 = acc[mt][nt][0], d1 = acc[mt][nt][1];
      float d2 = acc[mt][nt][2], d3 = acc[mt][nt][3];
      if (BIAS) {
        const float b0 = bias[col], b1 = bias[col + 1];
        d0 += b0; d1 += b1; d2 += b0; d3 += b1;
      }
      store2(Cz + (size_t)row0 * ldC + col, d0, d1);
      store2(Cz + (size_t)(row0 + 8) * ldC + col, d2, d3);
    }
  }
}

// ---------------------------------------------------------------------------
// fp32 -> fp16 conversion (vectorized 4 elems/thread)
// ---------------------------------------------------------------------------
__global__ __launch_bounds__(256) void cvt_kernel(
    const float* __restrict__ s, __half* __restrict__ d, int n4) {
  int i = blockIdx.x * blockDim.x + threadIdx.x;
  if (i < n4) {
    float4 f = ((const float4*)s)[i];
    ((__half2*)d)[2 * i] = __floats2half2_rn(f.x, f.y);
    ((__half2*)d)[2 * i + 1] = __floats2half2_rn(f.z, f.w);
  }
}

// ---------------------------------------------------------------------------
// Batched transpose (half): vt[b][n][k] = v[b][k][n]   (k=4096, n=256)
// ---------------------------------------------------------------------------
__global__ __launch_bounds__(256) void transpose_h(
    const __half* __restrict__ v, __half* __restrict__ vt) {
  __shared__ __half t[32][33];
  const int b = blockIdx.z;
  const int k0 = blockIdx.x * 32;
  const int n0 = blockIdx.y * 32;
  const int tx = threadIdx.x & 31;
  const int ty = threadIdx.x >> 5;  // 0..7
  const __half* src = v + (size_t)b * 4096 * 256;
  __half* dst = vt + (size_t)b * 256 * 4096;
#pragma unroll
  for (int i = 0; i < 32; i += 8)
    t[ty + i][tx] = src[(size_t)(k0 + ty + i) * 256 + n0 + tx];
  __syncthreads();
#pragma unroll
  for (int i = 0; i < 32; i += 8)
    dst[(size_t)(n0 + ty + i) * 4096 + k0 + tx] = t[tx][ty + i];
}

// ---------------------------------------------------------------------------
// Fused length-mask + scale(1/16) + softmax. Reads fp32 scores, writes half
// probs. Masked entries -> exp underflow -> exactly 0 (matches reference).
// ---------------------------------------------------------------------------
__global__ __launch_bounds__(256) void softmax_mask_kernel(
    const float* __restrict__ scores, __half* __restrict__ probs,
    const int* __restrict__ mask) {
  const size_t row = blockIdx.x;
  const int len = mask[row];
  const float* r = scores + row * 4096u;
  __half* p = probs + row * 4096u;
  const int t = threadIdx.x;
  const int lane = t & 31;
  const int wid = t >> 5;

  __shared__ float sred[8];

  const float scale = 0.0625f;
  float v[16];
  float mx = -1e30f;
#pragma unroll
  for (int i = 0; i < 16; i++) {
    const int kk = t + i * 256;
    float s = (kk < len) ? r[kk] * scale : -1e30f;
    v[i] = s;
    mx = fmaxf(mx, s);
  }
#pragma unroll
  for (int o = 16; o; o >>= 1) mx = fmaxf(mx, __shfl_xor_sync(0xffffffffu, mx, o));
  if (lane == 0) sred[wid] = mx;
  __syncthreads();
  float bm = sred[0];
#pragma unroll
  for (int w = 1; w < 8; w++) bm = fmaxf(bm, sred[w]);
  __syncthreads();

  float e[16];
  float sum = 0.0f;
#pragma unroll
  for (int i = 0; i < 16; i++) {
    e[i] = __expf(v[i] - bm);
    sum += e[i];
  }
#pragma unroll
  for (int o = 16; o; o >>= 1) sum += __shfl_xor_sync(0xffffffffu, sum, o);
  if (lane == 0) sred[wid] = sum;
  __syncthreads();
  float bs = 0.0f;
#pragma unroll
  for (int w = 0; w < 8; w++) bs += sred[w];
  const float inv = 1.0f / bs;

#pragma unroll
  for (int i = 0; i < 16; i++) {
    const int kk = t + i * 256;
    p[kk] = __float2half_rn(e[i] * inv);
  }
}

// ---------------------------------------------------------------------------
// Launch
// ---------------------------------------------------------------------------
extern "C" void kernel_launch(void* const* d_in, const int* in_sizes, int n_in,
                              void* d_out, int out_size) {
  const float* queries = (const float*)d_in[0];
  const float* keys    = (const float*)d_in[1];
  const float* values  = (const float*)d_in[2];
  const int*   mask    = (const int*)d_in[3];
  const float* Wq = (const float*)d_in[4];
  const float* bq = (const float*)d_in[5];
  const float* Wk = (const float*)d_in[6];
  const float* bk = (const float*)d_in[7];
  const float* Wv = (const float*)d_in[8];
  const float* bv = (const float*)d_in[9];
  const float* Wo = (const float*)d_in[10];
  const float* bo = (const float*)d_in[11];
  float* out = (float*)d_out;

  __half *xq, *xk, *xv, *wq, *wk, *wv, *wo;
  __half *qh, *kh, *vh, *vth, *atth, *ph;
  float* sc;
  cudaGetSymbolAddress((void**)&xq, g_xq);
  cudaGetSymbolAddress((void**)&xk, g_xk);
  cudaGetSymbolAddress((void**)&xv, g_xv);
  cudaGetSymbolAddress((void**)&wq, g_wq);
  cudaGetSymbolAddress((void**)&wk, g_wk);
  cudaGetSymbolAddress((void**)&wv, g_wv);
  cudaGetSymbolAddress((void**)&wo, g_wo);
  cudaGetSymbolAddress((void**)&qh, g_qh);
  cudaGetSymbolAddress((void**)&kh, g_kh);
  cudaGetSymbolAddress((void**)&vh, g_vh);
  cudaGetSymbolAddress((void**)&vth, g_vth);
  cudaGetSymbolAddress((void**)&atth, g_atth);
  cudaGetSymbolAddress((void**)&ph, g_ph);
  cudaGetSymbolAddress((void**)&sc, g_scores);

  cudaFuncSetAttribute(hgemm<true, __half>,
                       cudaFuncAttributeMaxDynamicSharedMemorySize, SMEM_TOTAL);
  cudaFuncSetAttribute(hgemm<false, float>,
                       cudaFuncAttributeMaxDynamicSharedMemorySize, SMEM_TOTAL);
  cudaFuncSetAttribute(hgemm<false, __half>,
                       cudaFuncAttributeMaxDynamicSharedMemorySize, SMEM_TOTAL);
  cudaFuncSetAttribute(hgemm<true, float>,
                       cudaFuncAttributeMaxDynamicSharedMemorySize, SMEM_TOTAL);

  const long long QD = 4096LL * 256;
  const long long QK = 4096LL * 4096;
  dim3 blk(256);

  // fp32 -> fp16 conversions
  const int NTOK4 = 4 * 4096 * 256 / 4;  // 1,048,576
  cvt_kernel<<<(NTOK4 + 255) / 256, blk>>>(queries, xq, NTOK4);
  cvt_kernel<<<(NTOK4 + 255) / 256, blk>>>(keys, xk, NTOK4);
  cvt_kernel<<<(NTOK4 + 255) / 256, blk>>>(values, xv, NTOK4);
  const int NW4 = 65536 / 4;
  cvt_kernel<<<(NW4 + 255) / 256, blk>>>(Wq, wq, NW4);
  cvt_kernel<<<(NW4 + 255) / 256, blk>>>(Wk, wk, NW4);
  cvt_kernel<<<(NW4 + 255) / 256, blk>>>(Wv, wv, NW4);
  cvt_kernel<<<(NW4 + 255) / 256, blk>>>(Wo, wo, NW4);

  // Projections: X[16384,256] @ W[256,256]^T + b -> half
  dim3 gProj(2, 128, 1);
  hgemm<true, __half><<<gProj, blk, SMEM_TOTAL>>>(
      xq, wq, bq, qh, 256, 256, 256, 256, 0, 0, 0);
  hgemm<true, __half><<<gProj, blk, SMEM_TOTAL>>>(
      xk, wk, bk, kh, 256, 256, 256, 256, 0, 0, 0);
  hgemm<true, __half><<<gProj, blk, SMEM_TOTAL>>>(
      xv, wv, bv, vh, 256, 256, 256, 256, 0, 0, 0);

  // vT for PV GEMM
  transpose_h<<<dim3(128, 8, 4), blk>>>(vh, vth);

  // Scores: per batch, S[4096,4096] = q @ k^T -> fp32
  hgemm<false, float><<<dim3(32, 32, 4), blk, SMEM_TOTAL>>>(
      qh, kh, nullptr, sc, 256, 256, 256, 4096, QD, QD, QK);

  // Mask + scale + softmax: fp32 in, half probs out
  softmax_mask_kernel<<<16384, 256>>>(sc, ph, mask);

  // att: per batch, att[4096,256] = P[4096,4096] @ vT[256,4096]^T -> half
  hgemm<false, __half><<<dim3(2, 32, 4), blk, SMEM_TOTAL>>>(
      ph, vth, nullptr, atth, 4096, 4096, 4096, 256, QK, QD, QD);

  // Output projection: out = att @ Wo^T + bo -> fp32
  hgemm<true, float><<<gProj, blk, SMEM_TOTAL>>>(
      atth, wo, bo, out, 256, 256, 256, 256, 0, 0, 0);
}

// round 9
// speedup vs baseline: 1.7254x; 1.6177x over previous
#include <cuda_runtime.h>
#include <cuda_fp16.h>
#include <cstdint>
#include <math.h>

// ---------------------------------------------------------------------------
// B=4, Q=K=4096, D=IN=256.
// R8: flash-attention fusion. Pipeline:
//   cvt inputs/weights -> half
//   qh/kh/vh = proj(x) (hgemm m16n8k16, bias)   ; vth = vh^T
//   flash_attn: S=q@k^T, mask(len)+/16, online softmax, O=P@V  (one kernel,
//               no scores/probs DRAM round trip)
//   out = atth @ Wo^T + bo
// ---------------------------------------------------------------------------

__device__ __half g_xq[4u * 4096u * 256u];
__device__ __half g_xk[4u * 4096u * 256u];
__device__ __half g_xv[4u * 4096u * 256u];
__device__ __half g_wq[65536], g_wk[65536], g_wv[65536], g_wo[65536];
__device__ __half g_qh[4u * 4096u * 256u];
__device__ __half g_kh[4u * 4096u * 256u];
__device__ __half g_vh[4u * 4096u * 256u];
__device__ __half g_vth[4u * 4096u * 256u];
__device__ __half g_atth[4u * 4096u * 256u];

// ======================= helpers =======================
__device__ __forceinline__ uint32_t smem_u32(const void* p) {
  uint32_t a;
  asm("{ .reg .u64 t; cvta.to.shared.u64 t, %1; cvt.u32.u64 %0, t; }"
      : "=r"(a) : "l"(p));
  return a;
}
__device__ __forceinline__ void cp16(uint32_t s, const void* g) {
  asm volatile("cp.async.cg.shared.global [%0], [%1], 16;\n" ::"r"(s), "l"(g));
}
__device__ __forceinline__ void cp_commit() {
  asm volatile("cp.async.commit_group;\n" ::: "memory");
}
template <int N>
__device__ __forceinline__ void cp_wait() {
  asm volatile("cp.async.wait_group %0;\n" ::"n"(N) : "memory");
}
__device__ __forceinline__ void mma16(float* d, const uint32_t* a, const uint32_t* b) {
  asm volatile(
      "mma.sync.aligned.m16n8k16.row.col.f32.f16.f16.f32 "
      "{%0,%1,%2,%3}, {%4,%5,%6,%7}, {%8,%9}, {%0,%1,%2,%3};"
      : "+f"(d[0]), "+f"(d[1]), "+f"(d[2]), "+f"(d[3])
      : "r"(a[0]), "r"(a[1]), "r"(a[2]), "r"(a[3]), "r"(b[0]), "r"(b[1]));
}
__device__ __forceinline__ uint32_t pack_half2(float a, float b) {
  __half2 h = __floats2half2_rn(a, b);
  return *(uint32_t*)&h;
}
__device__ __forceinline__ void store2(float* p, float d0, float d1) {
  float2 v; v.x = d0; v.y = d1;
  *(float2*)p = v;
}
__device__ __forceinline__ void store2(__half* p, float d0, float d1) {
  *(__half2*)p = __floats2half2_rn(d0, d1);
}

// ---------------------------------------------------------------------------
// fp16 GEMM (R7, proven): C[M,N] = A[M,Kd] @ B[N,Kd]^T (+ bias)
// ---------------------------------------------------------------------------
#define S32 20
#define TILE_WORDS (128 * S32)
#define STAGE_BYTES (2 * TILE_WORDS * 4)
#define GEMM_SMEM (2 * STAGE_BYTES)

template <bool BIAS, typename OutT>
__global__ void __launch_bounds__(256, 2) hgemm(
    const __half* __restrict__ A, const __half* __restrict__ B,
    const float* __restrict__ bias, OutT* __restrict__ C,
    int Kd, int ldA, int ldB, int ldC,
    long long sA, long long sB, long long sC) {
  extern __shared__ char dyn_smem[];
  const uint32_t smem_base = smem_u32(dyn_smem);
  const int tid = threadIdx.x;
  const int lane = tid & 31;
  const int wid = tid >> 5;
  const int wm = wid & 1;
  const int wn = wid >> 1;
  const long long z = blockIdx.z;
  const int bm = blockIdx.y * 128;
  const int bn = blockIdx.x * 128;

  const __half* gA = A + z * sA + (size_t)bm * ldA;
  const __half* gB = B + z * sB + (size_t)bn * ldB;

  float acc[4][4][4];
#pragma unroll
  for (int i = 0; i < 4; i++)
#pragma unroll
    for (int j = 0; j < 4; j++)
#pragma unroll
      for (int p = 0; p < 4; p++) acc[i][j][p] = 0.0f;

  const int ldRow = tid & 127;
  const bool isB = tid >= 128;
  const __half* gRowBase = (isB ? gB : gA);
  const int ldLd = isB ? ldB : ldA;
  const uint32_t sRowOff = (isB ? STAGE_BYTES / 2 : 0) + ldRow * (S32 * 4);

  auto load_tiles = [&](int stage, int k0) {
    const uint32_t s0 = smem_base + stage * STAGE_BYTES + sRowOff;
    const __half* g0 = gRowBase + (size_t)ldRow * ldLd + k0;
#pragma unroll
    for (int ch = 0; ch < 4; ch++) cp16(s0 + ch * 16, g0 + ch * 8);
    cp_commit();
  };

  const int g = lane >> 2;
  const int c = lane & 3;

  const int KT = Kd >> 5;
  load_tiles(0, 0);
  for (int it = 0; it < KT; ++it) {
    const int buf = it & 1;
    if (it + 1 < KT) {
      load_tiles(buf ^ 1, (it + 1) << 5);
      cp_wait<1>();
    } else {
      cp_wait<0>();
    }
    __syncthreads();

    const uint32_t* As32 = (const uint32_t*)(dyn_smem + buf * STAGE_BYTES);
    const uint32_t* Bs32 = As32 + TILE_WORDS;

#pragma unroll
    for (int kk = 0; kk < 2; ++kk) {
      const int ko = kk * 8;
      uint32_t af[4][4], bf[4][2];
#pragma unroll
      for (int mt = 0; mt < 4; mt++) {
        const int base = (wm * 64 + mt * 16 + g) * S32 + c + ko;
        af[mt][0] = As32[base];
        af[mt][1] = As32[base + 8 * S32];
        af[mt][2] = As32[base + 4];
        af[mt][3] = As32[base + 8 * S32 + 4];
      }
#pragma unroll
      for (int nt = 0; nt < 4; nt++) {
        const int base = (wn * 32 + nt * 8 + g) * S32 + c + ko;
        bf[nt][0] = Bs32[base];
        bf[nt][1] = Bs32[base + 4];
      }
#pragma unroll
      for (int mt = 0; mt < 4; mt++)
#pragma unroll
        for (int nt = 0; nt < 4; nt++) mma16(acc[mt][nt], af[mt], bf[nt]);
    }
    __syncthreads();
  }

  OutT* Cz = C + z * sC;
  const int c2 = c * 2;
#pragma unroll
  for (int mt = 0; mt < 4; mt++) {
    const int row0 = bm + wm * 64 + mt * 16 + g;
#pragma unroll
    for (int nt = 0; nt < 4; nt++) {
      const int col = bn + wn * 32 + nt * 8 + c2;
      float d0 = acc[mt][nt][0], d1 = acc[mt][nt][1];
      float d2 = acc[mt][nt][2], d3 = acc[mt][nt][3];
      if (BIAS) {
        const float b0 = bias[col], b1 = bias[col + 1];
        d0 += b0; d1 += b1; d2 += b0; d3 += b1;
      }
      store2(Cz + (size_t)row0 * ldC + col, d0, d1);
      store2(Cz + (size_t)(row0 + 8) * ldC + col, d2, d3);
    }
  }
}

// ---------------------------------------------------------------------------
// Flash attention: per CTA 128 queries x all 4096 keys (tiles of 64).
// 8 warps x 16 rows. qh/kh: [z][row][256] half; vth: [z][d=256][kk=4096] half.
// Output atth: [z][row][256] half (= P @ V, P = softmax(mask(S)/16)).
// smem: Q 128x(528B) + K 2x 64x(528B) + V 2x 256x(144B) = 208896 B.
// ---------------------------------------------------------------------------
#define OFF_Q 0
#define OFF_K0 (128 * 528)              // 67584
#define OFF_K1 (OFF_K0 + 64 * 528)      // 101376
#define OFF_V0 (OFF_K1 + 64 * 528)      // 135168
#define OFF_V1 (OFF_V0 + 256 * 144)     // 172032
#define FLASH_SMEM (OFF_V1 + 256 * 144) // 208896

__global__ void __launch_bounds__(256, 1) flash_attn(
    const __half* __restrict__ qh, const __half* __restrict__ kh,
    const __half* __restrict__ vth, const int* __restrict__ mask,
    __half* __restrict__ atth) {
  extern __shared__ char sm[];
  const uint32_t sb = smem_u32(sm);
  const int tid = threadIdx.x;
  const int lane = tid & 31;
  const int w = tid >> 5;
  const int g = lane >> 2;
  const int c = lane & 3;
  const int z = blockIdx.y;
  const int bm = blockIdx.x * 128;

  const __half* qp = qh + ((size_t)z * 4096 + bm) * 256;
  const __half* kp = kh + (size_t)z * 4096 * 256;
  const __half* vp = vth + (size_t)z * 256 * 4096;

  __shared__ int s_ctamax;
  if (tid == 0) s_ctamax = 0;
  __syncthreads();

  const int lenA = mask[z * 4096 + bm + w * 16 + g];
  const int lenB = mask[z * 4096 + bm + w * 16 + 8 + g];
  int wmax = max(lenA, lenB);
#pragma unroll
  for (int o = 4; o < 32; o <<= 1) wmax = max(wmax, __shfl_xor_sync(0xffffffffu, wmax, o));
  if (lane == 0) atomicMax(&s_ctamax, wmax);

  // Q tile: 128 rows x 512B (stride 528B)
#pragma unroll
  for (int i = 0; i < 16; i++) {
    const int idx = tid + i * 256;
    const int row = idx >> 5, ch = idx & 31;
    cp16(sb + OFF_Q + row * 528 + ch * 16, qp + (size_t)row * 256 + ch * 8);
  }
  cp_commit();

  auto load_kv = [&](int stage, int kt) {
    const uint32_t ko = sb + (stage ? OFF_K1 : OFF_K0);
    const uint32_t vo = sb + (stage ? OFF_V1 : OFF_V0);
#pragma unroll
    for (int i = 0; i < 8; i++) {
      const int idx = tid + i * 256;
      const int row = idx >> 5, ch = idx & 31;  // 64 rows x 32 chunks
      cp16(ko + row * 528 + ch * 16, kp + (size_t)(kt * 64 + row) * 256 + ch * 8);
    }
#pragma unroll
    for (int i = 0; i < 8; i++) {
      const int idx = tid + i * 256;
      const int row = idx >> 3, ch = idx & 7;  // 256 rows x 8 chunks
      cp16(vo + row * 144 + ch * 16, vp + (size_t)row * 4096 + kt * 64 + ch * 8);
    }
    cp_commit();
  };

  load_kv(0, 0);
  __syncthreads();  // s_ctamax visible
  const int NT = (s_ctamax + 63) >> 6;

  float O[32][4];
#pragma unroll
  for (int i = 0; i < 32; i++)
#pragma unroll
    for (int j = 0; j < 4; j++) O[i][j] = 0.0f;
  float m0 = -1e30f, m1 = -1e30f, l0 = 0.0f, l1 = 0.0f;

  for (int kt = 0; kt < NT; kt++) {
    const int buf = kt & 1;
    if (kt + 1 < NT) {
      load_kv(buf ^ 1, kt + 1);
      cp_wait<1>();
    } else {
      cp_wait<0>();
    }
    __syncthreads();

    if (kt * 64 < wmax) {
      // ---- S = Q @ K^T (16 rows x 64 keys per warp) ----
      float S[8][4];
#pragma unroll
      for (int nt = 0; nt < 8; nt++)
#pragma unroll
        for (int j = 0; j < 4; j++) S[nt][j] = 0.0f;

      const uint32_t* Qs = (const uint32_t*)(sm + OFF_Q) + (w * 16 + g) * 132 + c;
      const uint32_t* Ks =
          (const uint32_t*)(sm + (buf ? OFF_K1 : OFF_K0)) + g * 132 + c;
#pragma unroll
      for (int ks = 0; ks < 16; ks++) {
        uint32_t a[4];
        a[0] = Qs[ks * 8];
        a[1] = Qs[ks * 8 + 8 * 132];
        a[2] = Qs[ks * 8 + 4];
        a[3] = Qs[ks * 8 + 8 * 132 + 4];
#pragma unroll
        for (int nt = 0; nt < 8; nt++) {
          uint32_t b[2];
          b[0] = Ks[nt * 8 * 132 + ks * 8];
          b[1] = Ks[nt * 8 * 132 + ks * 8 + 4];
          mma16(S[nt], a, b);
        }
      }

      // ---- mask + scale(1/16) + online softmax ----
      const int kb = kt * 64;
      float tmax0 = -1e30f, tmax1 = -1e30f;
#pragma unroll
      for (int nt = 0; nt < 8; nt++) {
        const int col0 = kb + nt * 8 + c * 2;
        const int col1 = col0 + 1;
        float s00 = (col0 < lenA) ? S[nt][0] * 0.0625f : -1e30f;
        float s01 = (col1 < lenA) ? S[nt][1] * 0.0625f : -1e30f;
        float s10 = (col0 < lenB) ? S[nt][2] * 0.0625f : -1e30f;
        float s11 = (col1 < lenB) ? S[nt][3] * 0.0625f : -1e30f;
        S[nt][0] = s00; S[nt][1] = s01; S[nt][2] = s10; S[nt][3] = s11;
        tmax0 = fmaxf(tmax0, fmaxf(s00, s01));
        tmax1 = fmaxf(tmax1, fmaxf(s10, s11));
      }
      tmax0 = fmaxf(tmax0, __shfl_xor_sync(0xffffffffu, tmax0, 1));
      tmax0 = fmaxf(tmax0, __shfl_xor_sync(0xffffffffu, tmax0, 2));
      tmax1 = fmaxf(tmax1, __shfl_xor_sync(0xffffffffu, tmax1, 1));
      tmax1 = fmaxf(tmax1, __shfl_xor_sync(0xffffffffu, tmax1, 2));

      const float mn0 = fmaxf(m0, tmax0), mn1 = fmaxf(m1, tmax1);
      const float al0 = __expf(m0 - mn0), al1 = __expf(m1 - mn1);
      m0 = mn0; m1 = mn1;

      float sum0 = 0.0f, sum1 = 0.0f;
#pragma unroll
      for (int nt = 0; nt < 8; nt++) {
        S[nt][0] = __expf(S[nt][0] - mn0);
        S[nt][1] = __expf(S[nt][1] - mn0);
        S[nt][2] = __expf(S[nt][2] - mn1);
        S[nt][3] = __expf(S[nt][3] - mn1);
        sum0 += S[nt][0] + S[nt][1];
        sum1 += S[nt][2] + S[nt][3];
      }
      sum0 += __shfl_xor_sync(0xffffffffu, sum0, 1);
      sum0 += __shfl_xor_sync(0xffffffffu, sum0, 2);
      sum1 += __shfl_xor_sync(0xffffffffu, sum1, 1);
      sum1 += __shfl_xor_sync(0xffffffffu, sum1, 2);
      l0 = l0 * al0 + sum0;
      l1 = l1 * al1 + sum1;

#pragma unroll
      for (int nt2 = 0; nt2 < 32; nt2++) {
        O[nt2][0] *= al0; O[nt2][1] *= al0;
        O[nt2][2] *= al1; O[nt2][3] *= al1;
      }

      // ---- P fragments (C-layout -> A-fragment, FA2 mapping) ----
      uint32_t pa[4][4];
#pragma unroll
      for (int ks2 = 0; ks2 < 4; ks2++) {
        pa[ks2][0] = pack_half2(S[2 * ks2][0], S[2 * ks2][1]);
        pa[ks2][1] = pack_half2(S[2 * ks2][2], S[2 * ks2][3]);
        pa[ks2][2] = pack_half2(S[2 * ks2 + 1][0], S[2 * ks2 + 1][1]);
        pa[ks2][3] = pack_half2(S[2 * ks2 + 1][2], S[2 * ks2 + 1][3]);
      }

      // ---- O += P @ V ----
      const uint32_t* Vs =
          (const uint32_t*)(sm + (buf ? OFF_V1 : OFF_V0)) + g * 36 + c;
#pragma unroll
      for (int ks2 = 0; ks2 < 4; ks2++) {
#pragma unroll
        for (int nt2 = 0; nt2 < 32; nt2++) {
          uint32_t b[2];
          b[0] = Vs[nt2 * 8 * 36 + ks2 * 8];
          b[1] = Vs[nt2 * 8 * 36 + ks2 * 8 + 4];
          mma16(O[nt2], pa[ks2], b);
        }
      }
    }
    __syncthreads();
  }

  // ---- epilogue: O / l -> half ----
  const float il0 = 1.0f / l0;
  const float il1 = 1.0f / l1;
  __half* op = atth + ((size_t)z * 4096 + bm + w * 16) * 256;
#pragma unroll
  for (int nt2 = 0; nt2 < 32; nt2++) {
    const int col = nt2 * 8 + c * 2;
    store2(op + (size_t)g * 256 + col, O[nt2][0] * il0, O[nt2][1] * il0);
    store2(op + (size_t)(g + 8) * 256 + col, O[nt2][2] * il1, O[nt2][3] * il1);
  }
}

// ---------------------------------------------------------------------------
// fp32 -> fp16 conversion
// ---------------------------------------------------------------------------
__global__ __launch_bounds__(256) void cvt_kernel(
    const float* __restrict__ s, __half* __restrict__ d, int n4) {
  int i = blockIdx.x * blockDim.x + threadIdx.x;
  if (i < n4) {
    float4 f = ((const float4*)s)[i];
    ((__half2*)d)[2 * i] = __floats2half2_rn(f.x, f.y);
    ((__half2*)d)[2 * i + 1] = __floats2half2_rn(f.z, f.w);
  }
}

// ---------------------------------------------------------------------------
// Batched transpose (half): vt[b][n][k] = v[b][k][n]   (k=4096, n=256)
// ---------------------------------------------------------------------------
__global__ __launch_bounds__(256) void transpose_h(
    const __half* __restrict__ v, __half* __restrict__ vt) {
  __shared__ __half t[32][33];
  const int b = blockIdx.z;
  const int k0 = blockIdx.x * 32;
  const int n0 = blockIdx.y * 32;
  const int tx = threadIdx.x & 31;
  const int ty = threadIdx.x >> 5;
  const __half* src = v + (size_t)b * 4096 * 256;
  __half* dst = vt + (size_t)b * 256 * 4096;
#pragma unroll
  for (int i = 0; i < 32; i += 8)
    t[ty + i][tx] = src[(size_t)(k0 + ty + i) * 256 + n0 + tx];
  __syncthreads();
#pragma unroll
  for (int i = 0; i < 32; i += 8)
    dst[(size_t)(n0 + ty + i) * 4096 + k0 + tx] = t[tx][ty + i];
}

// ---------------------------------------------------------------------------
// Launch
// ---------------------------------------------------------------------------
extern "C" void kernel_launch(void* const* d_in, const int* in_sizes, int n_in,
                              void* d_out, int out_size) {
  const float* queries = (const float*)d_in[0];
  const float* keys    = (const float*)d_in[1];
  const float* values  = (const float*)d_in[2];
  const int*   mask    = (const int*)d_in[3];
  const float* Wq = (const float*)d_in[4];
  const float* bq = (const float*)d_in[5];
  const float* Wk = (const float*)d_in[6];
  const float* bk = (const float*)d_in[7];
  const float* Wv = (const float*)d_in[8];
  const float* bv = (const float*)d_in[9];
  const float* Wo = (const float*)d_in[10];
  const float* bo = (const float*)d_in[11];
  float* out = (float*)d_out;

  __half *xq, *xk, *xv, *wq, *wk, *wv, *wo;
  __half *qh, *kh, *vh, *vth, *atth;
  cudaGetSymbolAddress((void**)&xq, g_xq);
  cudaGetSymbolAddress((void**)&xk, g_xk);
  cudaGetSymbolAddress((void**)&xv, g_xv);
  cudaGetSymbolAddress((void**)&wq, g_wq);
  cudaGetSymbolAddress((void**)&wk, g_wk);
  cudaGetSymbolAddress((void**)&wv, g_wv);
  cudaGetSymbolAddress((void**)&wo, g_wo);
  cudaGetSymbolAddress((void**)&qh, g_qh);
  cudaGetSymbolAddress((void**)&kh, g_kh);
  cudaGetSymbolAddress((void**)&vh, g_vh);
  cudaGetSymbolAddress((void**)&vth, g_vth);
  cudaGetSymbolAddress((void**)&atth, g_atth);

  cudaFuncSetAttribute(hgemm<true, __half>,
                       cudaFuncAttributeMaxDynamicSharedMemorySize, GEMM_SMEM);
  cudaFuncSetAttribute(hgemm<true, float>,
                       cudaFuncAttributeMaxDynamicSharedMemorySize, GEMM_SMEM);
  cudaFuncSetAttribute(flash_attn,
                       cudaFuncAttributeMaxDynamicSharedMemorySize, FLASH_SMEM);

  dim3 blk(256);

  // fp32 -> fp16
  const int NTOK4 = 4 * 4096 * 256 / 4;
  cvt_kernel<<<(NTOK4 + 255) / 256, blk>>>(queries, xq, NTOK4);
  cvt_kernel<<<(NTOK4 + 255) / 256, blk>>>(keys, xk, NTOK4);
  cvt_kernel<<<(NTOK4 + 255) / 256, blk>>>(values, xv, NTOK4);
  const int NW4 = 65536 / 4;
  cvt_kernel<<<(NW4 + 255) / 256, blk>>>(Wq, wq, NW4);
  cvt_kernel<<<(NW4 + 255) / 256, blk>>>(Wk, wk, NW4);
  cvt_kernel<<<(NW4 + 255) / 256, blk>>>(Wv, wv, NW4);
  cvt_kernel<<<(NW4 + 255) / 256, blk>>>(Wo, wo, NW4);

  // Projections -> half
  dim3 gProj(2, 128, 1);
  hgemm<true, __half><<<gProj, blk, GEMM_SMEM>>>(
      xq, wq, bq, qh, 256, 256, 256, 256, 0, 0, 0);
  hgemm<true, __half><<<gProj, blk, GEMM_SMEM>>>(
      xk, wk, bk, kh, 256, 256, 256, 256, 0, 0, 0);
  hgemm<true, __half><<<gProj, blk, GEMM_SMEM>>>(
      xv, wv, bv, vh, 256, 256, 256, 256, 0, 0, 0);

  // vT for flash V tiles
  transpose_h<<<dim3(128, 8, 4), blk>>>(vh, vth);

  // Fused attention
  flash_attn<<<dim3(32, 4, 1), blk, FLASH_SMEM>>>(qh, kh, vth, mask, atth);

  // Output projection -> fp32
  hgemm<true, float><<<gProj, blk, GEMM_SMEM>>>(
      atth, wo, bo, out, 256, 256, 256, 256, 0, 0, 0);
}